// round 5
// baseline (speedup 1.0000x reference)
#include <cuda_runtime.h>
#include <cuda_fp16.h>

#define NNODES 50000
#define FDIM 36
#define ROWH 64                 // halves per row = 128 bytes
#define EMAX 800000
#define SY_STRIDE 40            // smem y row stride (floats, 160B)

// ---------------- persistent device scratch ----------------
__device__ __align__(16) __half g_hpA[NNODES * ROWH];
__device__ __align__(16) __half g_hpB[NNODES * ROWH];
__device__ __align__(16) float g_ald[NNODES * 4];
__device__ int g_deg[NNODES];
__device__ int g_rowstart[NNODES];
__device__ int g_rank[EMAX];
__device__ int g_col[EMAX];
__device__ int g_total;

__device__ __forceinline__ float lrelu(float x) { return fmaxf(x, 0.2f * x); }

// ---------------- CSR build ----------------
__global__ void zero_kernel() {
    int i = blockIdx.x * blockDim.x + threadIdx.x;
    if (i < NNODES) g_deg[i] = 0;
    if (i == 0) g_total = 0;
}

__global__ void count_kernel(const int* __restrict__ dst, int E) {
    int i = blockIdx.x * blockDim.x + threadIdx.x;
    if (i < E) g_rank[i] = atomicAdd(&g_deg[dst[i]], 1);
}

__global__ void assign_kernel() {
    int i = blockIdx.x * blockDim.x + threadIdx.x;
    int lane = threadIdx.x & 31;
    int v = (i < NNODES) ? g_deg[i] : 0;
    int x = v;
    #pragma unroll
    for (int off = 1; off < 32; off <<= 1) {
        int t = __shfl_up_sync(0xffffffffu, x, off);
        if (lane >= off) x += t;
    }
    int wsum = __shfl_sync(0xffffffffu, x, 31);
    int base = 0;
    if (lane == 31) base = atomicAdd(&g_total, wsum);
    base = __shfl_sync(0xffffffffu, base, 31);
    if (i < NNODES) g_rowstart[i] = base + x - v;
}

__global__ void scatter_kernel(const int* __restrict__ src, const int* __restrict__ dst, int E) {
    int i = blockIdx.x * blockDim.x + threadIdx.x;
    if (i < E) {
        int d = dst[i];
        g_col[g_rowstart[d] + g_rank[i]] = src[i];
    }
}

// ---------------- helpers ----------------
union U4H {
    uint4 u;
    __half2 h2[4];
};

__device__ __forceinline__ void acc8(float acc[8], uint4 v, float wlo, float whi) {
    U4H c; c.u = v;
    float2 f0 = __half22float2(c.h2[0]);
    float2 f1 = __half22float2(c.h2[1]);
    float2 f2 = __half22float2(c.h2[2]);
    float2 f3 = __half22float2(c.h2[3]);
    acc[0] = fmaf(wlo, f0.x, acc[0]); acc[1] = fmaf(wlo, f0.y, acc[1]);
    acc[2] = fmaf(wlo, f1.x, acc[2]); acc[3] = fmaf(wlo, f1.y, acc[3]);
    acc[4] = fmaf(whi, f2.x, acc[4]); acc[5] = fmaf(whi, f2.y, acc[5]);
    acc[6] = fmaf(whi, f3.x, acc[6]); acc[7] = fmaf(whi, f3.y, acc[7]);
}

__device__ __forceinline__ uint4 pack8(const float* v) {
    U4H c;
    c.h2[0] = __floats2half2_rn(v[0], v[1]);
    c.h2[1] = __floats2half2_rn(v[2], v[3]);
    c.h2[2] = __floats2half2_rn(v[4], v[5]);
    c.h2[3] = __floats2half2_rn(v[6], v[7]);
    return c.u;
}

// ---------------- layer-0 transform: h = x @ W0^T (in=24), write fp16 rows ----------------
__global__ void transform0_kernel(const float* __restrict__ xin,
                                  const float* __restrict__ W,
                                  const float* __restrict__ a_src,
                                  const float* __restrict__ a_dst,
                                  __half* __restrict__ hout) {
    __shared__ float sW[FDIM * 24];
    __shared__ float sas[FDIM], sad[FDIM];
    int tid = threadIdx.x;
    for (int i = tid; i < FDIM * 24; i += blockDim.x) sW[i] = W[i];
    if (tid < FDIM) { sas[tid] = a_src[tid]; sad[tid] = a_dst[tid]; }
    __syncthreads();
    int n = blockIdx.x * blockDim.x + tid;
    if (n >= NNODES) return;

    float yr[24];
    const float4* xv = (const float4*)(xin + n * 24);
    #pragma unroll
    for (int q = 0; q < 6; q++) {
        float4 v = xv[q];
        yr[4 * q] = v.x; yr[4 * q + 1] = v.y; yr[4 * q + 2] = v.z; yr[4 * q + 3] = v.w;
    }

    float h[FDIM + 4];
    float als0 = 0, als1 = 0, als2 = 0, ald0 = 0, ald1 = 0, ald2 = 0;
    #pragma unroll
    for (int o = 0; o < FDIM; o++) {
        float a = 0;
        #pragma unroll
        for (int i = 0; i < 24; i++) a = fmaf(yr[i], sW[o * 24 + i], a);
        h[o] = a;
        float as = a * sas[o], av = a * sad[o];
        if (o < 12)      { als0 += as; ald0 += av; }
        else if (o < 24) { als1 += as; ald1 += av; }
        else             { als2 += as; ald2 += av; }
    }
    h[36] = 0.f; h[37] = 0.f; h[38] = 0.f; h[39] = 0.f;

    char* row = (char*)hout + ((size_t)n << 7);
    #pragma unroll
    for (int q = 0; q < 5; q++) *(uint4*)(row + 16 * q) = pack8(h + 8 * q);
    *(float4*)(row + 80) = make_float4(als0, als1, als2, 0.f);
    *(float4*)&g_ald[n * 4] = make_float4(ald0, ald1, ald2, 0.f);
}

// ---------------- 4-lane aggregation over fp16 128B rows ----------------
// lane k accumulates features [8k,8k+8); lane0 additionally [32,40).
__device__ __forceinline__ void aggregate_h(int n, int lk, unsigned qmask,
                                            const __half* __restrict__ hin,
                                            float accM[8], float accX[8],
                                            float& s0, float& s1, float& s2) {
    int beg = g_rowstart[n];
    int end = beg + g_deg[n];
    float4 ad = *(const float4*)&g_ald[n * 4];
    const char* base = (const char*)hin;

    // self loop
    const char* selfrow = base + ((size_t)n << 7);
    float4 av = *(const float4*)(selfrow + 80);
    float p0 = __expf(lrelu(av.x + ad.x));
    float p1 = __expf(lrelu(av.y + ad.y));
    float p2 = __expf(lrelu(av.z + ad.z));
    s0 = p0; s1 = p1; s2 = p2;

    #pragma unroll
    for (int i = 0; i < 8; i++) { accM[i] = 0.f; accX[i] = 0.f; }
    {
        float wlo = (lk < 2) ? p0 : ((lk == 2) ? p1 : p2);
        float whi = (lk == 0) ? p0 : ((lk < 3) ? p1 : p2);
        acc8(accM, *(const uint4*)(selfrow + 16 * lk), wlo, whi);
        if (lk == 0) acc8(accX, *(const uint4*)(selfrow + 64), p2, p2);
    }

    for (int t0 = beg; t0 < end; t0 += 4) {
        int ew = t0 + lk;
        int ec = min(ew, end - 1);
        int cw = g_col[ec];
        const char* rw = base + ((size_t)cw << 7);
        float4 aw = *(const float4*)(rw + 80);
        float w0 = 0.f, w1 = 0.f, w2 = 0.f;
        if (ew < end) {
            w0 = __expf(lrelu(aw.x + ad.x));
            w1 = __expf(lrelu(aw.y + ad.y));
            w2 = __expf(lrelu(aw.z + ad.z));
        }
        #pragma unroll
        for (int j = 0; j < 4; j++) {
            int sn   = __shfl_sync(qmask, cw, j, 4);
            float q0 = __shfl_sync(qmask, w0, j, 4);
            float q1 = __shfl_sync(qmask, w1, j, 4);
            float q2 = __shfl_sync(qmask, w2, j, 4);
            s0 += q0; s1 += q1; s2 += q2;
            const char* r = base + ((size_t)sn << 7);
            float ulo = (lk < 2) ? q0 : ((lk == 2) ? q1 : q2);
            float uhi = (lk == 0) ? q0 : ((lk < 3) ? q1 : q2);
            acc8(accM, *(const uint4*)(r + 16 * lk), ulo, uhi);
            if (lk == 0) acc8(accX, *(const uint4*)(r + 64), q2, q2);
        }
    }
}

// layers 0-2: aggregate + relu + fused next-layer transform -> hout
__global__ void __launch_bounds__(256)
gather_fused_kernel(const __half* __restrict__ hin,
                    __half* __restrict__ hout,
                    const float* __restrict__ bias,
                    const float* __restrict__ Wn,
                    const float* __restrict__ a_src,
                    const float* __restrict__ a_dst) {
    __shared__ __align__(16) float sy[64 * SY_STRIDE];
    __shared__ float sW[FDIM * FDIM];
    __shared__ float sb[FDIM], sas[FDIM], sad[FDIM];
    int tid = threadIdx.x;
    for (int i = tid; i < FDIM * FDIM; i += blockDim.x) sW[i] = Wn[i];
    if (tid < FDIM) { sb[tid] = bias[tid]; sas[tid] = a_src[tid]; sad[tid] = a_dst[tid]; }
    __syncthreads();

    int t = blockIdx.x * blockDim.x + tid;
    int n = t >> 2;
    int lk = t & 3;
    if (n >= NNODES) return;
    unsigned qmask = 0xFu << ((tid & 31) & ~3);
    float* yrow = &sy[(tid >> 2) * SY_STRIDE];

    float accM[8], accX[8];
    float s0, s1, s2;
    aggregate_h(n, lk, qmask, hin, accM, accX, s0, s1, s2);

    float i0 = 1.f / (s0 + 1e-16f);
    float i1 = 1.f / (s1 + 1e-16f);
    float i2 = 1.f / (s2 + 1e-16f);
    float ilo = (lk < 2) ? i0 : ((lk == 2) ? i1 : i2);
    float ihi = (lk == 0) ? i0 : ((lk < 3) ? i1 : i2);

    // normalize + bias + relu -> shared
    {
        int ob = 8 * lk;
        float y8[8];
        #pragma unroll
        for (int k = 0; k < 4; k++) y8[k] = fmaxf(fmaf(accM[k], ilo, sb[ob + k]), 0.f);
        #pragma unroll
        for (int k = 4; k < 8; k++) y8[k] = fmaxf(fmaf(accM[k], ihi, sb[ob + k]), 0.f);
        *(float4*)&yrow[ob]     = make_float4(y8[0], y8[1], y8[2], y8[3]);
        *(float4*)&yrow[ob + 4] = make_float4(y8[4], y8[5], y8[6], y8[7]);
        if (lk == 0) {
            float4 yx = make_float4(fmaxf(fmaf(accX[0], i2, sb[32]), 0.f),
                                    fmaxf(fmaf(accX[1], i2, sb[33]), 0.f),
                                    fmaxf(fmaf(accX[2], i2, sb[34]), 0.f),
                                    fmaxf(fmaf(accX[3], i2, sb[35]), 0.f));
            *(float4*)&yrow[32] = yx;
        }
    }
    __syncwarp();

    float yv[36];
    #pragma unroll
    for (int q = 0; q < 9; q++) {
        float4 v = *(const float4*)&yrow[4 * q];
        yv[4 * q] = v.x; yv[4 * q + 1] = v.y; yv[4 * q + 2] = v.z; yv[4 * q + 3] = v.w;
    }

    // fused next-layer transform: lane computes outputs [8lk, 8lk+8); lane0 also [32,36)
    char* row = (char*)hout + ((size_t)n << 7);
    float plsA = 0, plsB = 0, pldA = 0, pldB = 0;   // first-4 / last-4 output partials
    float plsX = 0, pldX = 0;                        // lane0 extra (head2)
    {
        float h8[8];
        #pragma unroll
        for (int k = 0; k < 8; k++) {
            int o = 8 * lk + k;
            float a = 0;
            #pragma unroll
            for (int i = 0; i < FDIM; i++) a = fmaf(yv[i], sW[o * FDIM + i], a);
            h8[k] = a;
            float as = a * sas[o], av = a * sad[o];
            if (k < 4) { plsA += as; pldA += av; } else { plsB += as; pldB += av; }
        }
        *(uint4*)(row + 16 * lk) = pack8(h8);
        if (lk == 0) {
            float hx[8];
            #pragma unroll
            for (int k = 0; k < 4; k++) {
                int o = 32 + k;
                float a = 0;
                #pragma unroll
                for (int i = 0; i < FDIM; i++) a = fmaf(yv[i], sW[o * FDIM + i], a);
                hx[k] = a;
                plsX += a * sas[o]; pldX += a * sad[o];
            }
            hx[4] = hx[5] = hx[6] = hx[7] = 0.f;
            *(uint4*)(row + 64) = pack8(hx);
        }
    }
    // map partials to heads: lane0: A+B->h0, X->h2 ; lane1: A->h0, B->h1 ; lane2: A+B->h1 ; lane3: A+B->h2
    float pls0 = 0, pls1 = 0, pls2 = 0, pld0 = 0, pld1 = 0, pld2 = 0;
    if (lk == 0)      { pls0 = plsA + plsB; pld0 = pldA + pldB; pls2 = plsX; pld2 = pldX; }
    else if (lk == 1) { pls0 = plsA; pld0 = pldA; pls1 = plsB; pld1 = pldB; }
    else if (lk == 2) { pls1 = plsA + plsB; pld1 = pldA + pldB; }
    else              { pls2 = plsA + plsB; pld2 = pldA + pldB; }
    #pragma unroll
    for (int off = 1; off < 4; off <<= 1) {
        pls0 += __shfl_xor_sync(qmask, pls0, off, 4);
        pls1 += __shfl_xor_sync(qmask, pls1, off, 4);
        pls2 += __shfl_xor_sync(qmask, pls2, off, 4);
        pld0 += __shfl_xor_sync(qmask, pld0, off, 4);
        pld1 += __shfl_xor_sync(qmask, pld1, off, 4);
        pld2 += __shfl_xor_sync(qmask, pld2, off, 4);
    }
    if (lk == 1) *(float4*)(row + 80) = make_float4(pls0, pls1, pls2, 0.f);
    if (lk == 2) *(float4*)&g_ald[n * 4] = make_float4(pld0, pld1, pld2, 0.f);
}

// layer 3: aggregate + head-mean + bias + lin1 + lin2 -> out
__global__ void __launch_bounds__(256)
gather_last_kernel(const __half* __restrict__ hin,
                   const float* __restrict__ b3,
                   const float* __restrict__ lin1_w,
                   const float* __restrict__ lin1_b,
                   const float* __restrict__ lin2_w,
                   const float* __restrict__ lin2_b,
                   float* __restrict__ out) {
    __shared__ __align__(16) float sy[64 * SY_STRIDE];
    __shared__ float sb[12], s1w[144], s1b[12], s2w[72], s2b[6];
    int tid = threadIdx.x;
    if (tid < 12) { sb[tid] = b3[tid]; s1b[tid] = lin1_b[tid]; }
    if (tid < 6) s2b[tid] = lin2_b[tid];
    for (int i = tid; i < 144; i += blockDim.x) s1w[i] = lin1_w[i];
    for (int i = tid; i < 72; i += blockDim.x) s2w[i] = lin2_w[i];
    __syncthreads();

    int t = blockIdx.x * blockDim.x + tid;
    int n = t >> 2;
    int lk = t & 3;
    if (n >= NNODES) return;
    unsigned qmask = 0xFu << ((tid & 31) & ~3);
    float* yrow = &sy[(tid >> 2) * SY_STRIDE];

    float accM[8], accX[8];
    float s0, s1, s2;
    aggregate_h(n, lk, qmask, hin, accM, accX, s0, s1, s2);

    float i0 = 1.f / (s0 + 1e-16f);
    float i1 = 1.f / (s1 + 1e-16f);
    float i2 = 1.f / (s2 + 1e-16f);
    float ilo = (lk < 2) ? i0 : ((lk == 2) ? i1 : i2);
    float ihi = (lk == 0) ? i0 : ((lk < 3) ? i1 : i2);

    int ob = 8 * lk;
    *(float4*)&yrow[ob]     = make_float4(accM[0] * ilo, accM[1] * ilo, accM[2] * ilo, accM[3] * ilo);
    *(float4*)&yrow[ob + 4] = make_float4(accM[4] * ihi, accM[5] * ihi, accM[6] * ihi, accM[7] * ihi);
    if (lk == 0)
        *(float4*)&yrow[32] = make_float4(accX[0] * i2, accX[1] * i2, accX[2] * i2, accX[3] * i2);
    __syncwarp();

    if (lk == 0) {
        float o12[12];
        #pragma unroll
        for (int o = 0; o < 12; o++)
            o12[o] = (yrow[o] + yrow[o + 12] + yrow[o + 24]) * (1.f / 3.f) + sb[o];
        float tt[12];
        #pragma unroll
        for (int j = 0; j < 12; j++) {
            float a = s1b[j];
            #pragma unroll
            for (int k = 0; k < 12; k++) a = fmaf(o12[k], s1w[j * 12 + k], a);
            tt[j] = a;
        }
        float r[6];
        #pragma unroll
        for (int i = 0; i < 6; i++) {
            float a = s2b[i];
            #pragma unroll
            for (int j = 0; j < 12; j++) a = fmaf(tt[j], s2w[i * 12 + j], a);
            r[i] = a;
        }
        float2* ov = (float2*)(out + n * 6);
        ov[0] = make_float2(r[0], r[1]);
        ov[1] = make_float2(r[2], r[3]);
        ov[2] = make_float2(r[4], r[5]);
    }
}

// ---------------- launch ----------------
extern "C" void kernel_launch(void* const* d_in, const int* in_sizes, int n_in,
                              void* d_out, int out_size) {
    const float* x = (const float*)d_in[0];
    const int* ei = (const int*)d_in[1];
    int E = in_sizes[1] / 2;
    const int* src = ei;
    const int* dst = ei + E;

    const float* W[4]   = {(const float*)d_in[2],  (const float*)d_in[6],
                           (const float*)d_in[10], (const float*)d_in[14]};
    const float* asr[4] = {(const float*)d_in[3],  (const float*)d_in[7],
                           (const float*)d_in[11], (const float*)d_in[15]};
    const float* adt[4] = {(const float*)d_in[4],  (const float*)d_in[8],
                           (const float*)d_in[12], (const float*)d_in[16]};
    const float* b[4]   = {(const float*)d_in[5],  (const float*)d_in[9],
                           (const float*)d_in[13], (const float*)d_in[17]};
    const float* lin1_w = (const float*)d_in[18];
    const float* lin1_b = (const float*)d_in[19];
    const float* lin2_w = (const float*)d_in[20];
    const float* lin2_b = (const float*)d_in[21];
    float* out = (float*)d_out;

    __half* hA; cudaGetSymbolAddress((void**)&hA, g_hpA);
    __half* hB; cudaGetSymbolAddress((void**)&hB, g_hpB);

    int nb = (NNODES + 255) / 256;
    int eb = (E + 255) / 256;
    zero_kernel<<<nb, 256>>>();
    count_kernel<<<eb, 256>>>(dst, E);
    assign_kernel<<<nb, 256>>>();
    scatter_kernel<<<eb, 256>>>(src, dst, E);

    transform0_kernel<<<nb, 256>>>(x, W[0], asr[0], adt[0], hA);

    int gb = (NNODES * 4 + 255) / 256;
    gather_fused_kernel<<<gb, 256>>>(hA, hB, b[0], W[1], asr[1], adt[1]);
    gather_fused_kernel<<<gb, 256>>>(hB, hA, b[1], W[2], asr[2], adt[2]);
    gather_fused_kernel<<<gb, 256>>>(hA, hB, b[2], W[3], asr[3], adt[3]);
    gather_last_kernel<<<gb, 256>>>(hB, b[3], lin1_w, lin1_b, lin2_w, lin2_b, out);
}

// round 6
// speedup vs baseline: 1.1037x; 1.1037x over previous
#include <cuda_runtime.h>

#define NNODES 50000
#define FDIM 36
#define ROWF 40                 // floats per h row (36 used, 160B stride)
#define EMAX 800000
#define SY_STRIDE 40

// ---------------- persistent device scratch ----------------
__device__ __align__(16) float g_hpA[NNODES * ROWF];
__device__ __align__(16) float g_hpB[NNODES * ROWF];
__device__ __align__(16) float g_als[NNODES * 4];
__device__ __align__(16) float g_ald[NNODES * 4];
__device__ __align__(16) float4 g_ew[EMAX];
__device__ int g_deg[NNODES];
__device__ int g_rowstart[NNODES];
__device__ int g_rank[EMAX];
__device__ int g_col[EMAX];
__device__ int g_dstj[EMAX];
__device__ int g_total;

__device__ __forceinline__ float lrelu(float x) { return fmaxf(x, 0.2f * x); }

// ---------------- CSR build ----------------
__global__ void zero_kernel() {
    int i = blockIdx.x * blockDim.x + threadIdx.x;
    if (i < NNODES) g_deg[i] = 0;
    if (i == 0) g_total = 0;
}

__global__ void count_kernel(const int* __restrict__ dst, int E) {
    int i = blockIdx.x * blockDim.x + threadIdx.x;
    if (i < E) g_rank[i] = atomicAdd(&g_deg[dst[i]], 1);
}

__global__ void assign_kernel() {
    int i = blockIdx.x * blockDim.x + threadIdx.x;
    int lane = threadIdx.x & 31;
    int v = (i < NNODES) ? g_deg[i] : 0;
    int x = v;
    #pragma unroll
    for (int off = 1; off < 32; off <<= 1) {
        int t = __shfl_up_sync(0xffffffffu, x, off);
        if (lane >= off) x += t;
    }
    int wsum = __shfl_sync(0xffffffffu, x, 31);
    int base = 0;
    if (lane == 31) base = atomicAdd(&g_total, wsum);
    base = __shfl_sync(0xffffffffu, base, 31);
    if (i < NNODES) g_rowstart[i] = base + x - v;
}

__global__ void scatter_kernel(const int* __restrict__ src, const int* __restrict__ dst, int E) {
    int i = blockIdx.x * blockDim.x + threadIdx.x;
    if (i < E) {
        int d = dst[i];
        int p = g_rowstart[d] + g_rank[i];
        g_col[p] = src[i];
        g_dstj[p] = d;
    }
}

// ---------------- per-layer edge weights: w = exp(lrelu(als[src]+ald[dst])) ----------------
__global__ void edgew_kernel(int E) {
    int j = blockIdx.x * blockDim.x + threadIdx.x;
    if (j >= E) return;
    int sn = g_col[j];
    int d  = g_dstj[j];
    float4 as = *(const float4*)&g_als[sn * 4];
    float4 ad = *(const float4*)&g_ald[d * 4];
    float w0 = __expf(lrelu(as.x + ad.x));
    float w1 = __expf(lrelu(as.y + ad.y));
    float w2 = __expf(lrelu(as.z + ad.z));
    g_ew[j] = make_float4(w0, w1, w2, __int_as_float(sn));
}

// ---------------- layer-0 transform: h = x @ W0^T (in=24) ----------------
__global__ void transform0_kernel(const float* __restrict__ xin,
                                  const float* __restrict__ W,
                                  const float* __restrict__ a_src,
                                  const float* __restrict__ a_dst,
                                  float* __restrict__ hout) {
    __shared__ float sW[FDIM * 24];
    __shared__ float sas[FDIM], sad[FDIM];
    int tid = threadIdx.x;
    for (int i = tid; i < FDIM * 24; i += blockDim.x) sW[i] = W[i];
    if (tid < FDIM) { sas[tid] = a_src[tid]; sad[tid] = a_dst[tid]; }
    __syncthreads();
    int n = blockIdx.x * blockDim.x + tid;
    if (n >= NNODES) return;

    float yr[24];
    const float4* xv = (const float4*)(xin + n * 24);
    #pragma unroll
    for (int q = 0; q < 6; q++) {
        float4 v = xv[q];
        yr[4 * q] = v.x; yr[4 * q + 1] = v.y; yr[4 * q + 2] = v.z; yr[4 * q + 3] = v.w;
    }

    float als0 = 0, als1 = 0, als2 = 0, ald0 = 0, ald1 = 0, ald2 = 0;
    float4* rowv = (float4*)(hout + n * ROWF);
    #pragma unroll
    for (int q = 0; q < 9; q++) {
        float4 hv;
        #pragma unroll
        for (int k = 0; k < 4; k++) {
            int o = q * 4 + k;
            float a = 0;
            #pragma unroll
            for (int i = 0; i < 24; i++) a = fmaf(yr[i], sW[o * 24 + i], a);
            ((float*)&hv)[k] = a;
            float as = a * sas[o], av = a * sad[o];
            if (q < 3)      { als0 += as; ald0 += av; }
            else if (q < 6) { als1 += as; ald1 += av; }
            else            { als2 += as; ald2 += av; }
        }
        rowv[q] = hv;
    }
    *(float4*)&g_als[n * 4] = make_float4(als0, als1, als2, 0.f);
    *(float4*)&g_ald[n * 4] = make_float4(ald0, ald1, ald2, 0.f);
}

// ---------------- 4-lane aggregation with precomputed edge weights ----------------
// lane lk accumulates quads {lk, lk+4}; lane 0 also quad 8.
__device__ __forceinline__ void aggregate4(int n, int lk, const float* __restrict__ hin,
                                           float4& accA, float4& accB, float4& accC,
                                           float& s0, float& s1, float& s2) {
    int beg = g_rowstart[n];
    int end = beg + g_deg[n];

    // self loop: compute own weight inline
    float4 as = *(const float4*)&g_als[n * 4];
    float4 ad = *(const float4*)&g_ald[n * 4];
    float p0 = __expf(lrelu(as.x + ad.x));
    float p1 = __expf(lrelu(as.y + ad.y));
    float p2 = __expf(lrelu(as.z + ad.z));
    s0 = p0; s1 = p1; s2 = p2;

    const float4* self = (const float4*)(hin + n * ROWF);
    float wA = (lk < 3) ? p0 : p1;
    float wB = (lk < 2) ? p1 : p2;
    {
        float4 vA = self[lk];
        float4 vB = self[lk + 4];
        accA = make_float4(wA * vA.x, wA * vA.y, wA * vA.z, wA * vA.w);
        accB = make_float4(wB * vB.x, wB * vB.y, wB * vB.z, wB * vB.w);
        if (lk == 0) {
            float4 vC = self[8];
            accC = make_float4(p2 * vC.x, p2 * vC.y, p2 * vC.z, p2 * vC.w);
        } else {
            accC = make_float4(0.f, 0.f, 0.f, 0.f);
        }
    }

    #pragma unroll 2
    for (int j = beg; j < end; j++) {
        float4 w4 = g_ew[j];                       // sequential, L1-friendly
        int sn = __float_as_int(w4.w);
        const float4* r = (const float4*)(hin + sn * ROWF);
        float4 vA = r[lk];
        float4 vB = r[lk + 4];
        s0 += w4.x; s1 += w4.y; s2 += w4.z;
        float uA = (lk < 3) ? w4.x : w4.y;
        float uB = (lk < 2) ? w4.y : w4.z;
        accA.x = fmaf(uA, vA.x, accA.x); accA.y = fmaf(uA, vA.y, accA.y);
        accA.z = fmaf(uA, vA.z, accA.z); accA.w = fmaf(uA, vA.w, accA.w);
        accB.x = fmaf(uB, vB.x, accB.x); accB.y = fmaf(uB, vB.y, accB.y);
        accB.z = fmaf(uB, vB.z, accB.z); accB.w = fmaf(uB, vB.w, accB.w);
        if (lk == 0) {
            float4 vC = r[8];
            accC.x = fmaf(w4.z, vC.x, accC.x); accC.y = fmaf(w4.z, vC.y, accC.y);
            accC.z = fmaf(w4.z, vC.z, accC.z); accC.w = fmaf(w4.z, vC.w, accC.w);
        }
    }
}

// layers 0-2: aggregate + relu + fused next-layer transform -> hout (+ new als/ald)
__global__ void __launch_bounds__(256)
gather_fused_kernel(const float* __restrict__ hin,
                    float* __restrict__ hout,
                    const float* __restrict__ bias,
                    const float* __restrict__ Wn,
                    const float* __restrict__ a_src,
                    const float* __restrict__ a_dst) {
    __shared__ __align__(16) float sy[64 * SY_STRIDE];
    __shared__ float sW[FDIM * FDIM];
    __shared__ float sb[FDIM], sas[FDIM], sad[FDIM];
    int tid = threadIdx.x;
    for (int i = tid; i < FDIM * FDIM; i += blockDim.x) sW[i] = Wn[i];
    if (tid < FDIM) { sb[tid] = bias[tid]; sas[tid] = a_src[tid]; sad[tid] = a_dst[tid]; }
    __syncthreads();

    int t = blockIdx.x * blockDim.x + tid;
    int n = t >> 2;
    int lk = t & 3;
    if (n >= NNODES) return;
    float* yrow = &sy[(tid >> 2) * SY_STRIDE];

    float4 accA, accB, accC;
    float s0, s1, s2;
    aggregate4(n, lk, hin, accA, accB, accC, s0, s1, s2);

    float i0 = 1.f / (s0 + 1e-16f);
    float i1 = 1.f / (s1 + 1e-16f);
    float i2 = 1.f / (s2 + 1e-16f);
    float invA = (lk < 3) ? i0 : i1;
    float invB = (lk < 2) ? i1 : i2;

    // normalized + bias + relu -> shared
    {
        int oA = 4 * lk, oB = 16 + 4 * lk;
        float4 yA = make_float4(fmaxf(fmaf(accA.x, invA, sb[oA + 0]), 0.f),
                                fmaxf(fmaf(accA.y, invA, sb[oA + 1]), 0.f),
                                fmaxf(fmaf(accA.z, invA, sb[oA + 2]), 0.f),
                                fmaxf(fmaf(accA.w, invA, sb[oA + 3]), 0.f));
        float4 yB = make_float4(fmaxf(fmaf(accB.x, invB, sb[oB + 0]), 0.f),
                                fmaxf(fmaf(accB.y, invB, sb[oB + 1]), 0.f),
                                fmaxf(fmaf(accB.z, invB, sb[oB + 2]), 0.f),
                                fmaxf(fmaf(accB.w, invB, sb[oB + 3]), 0.f));
        *(float4*)&yrow[oA] = yA;
        *(float4*)&yrow[oB] = yB;
        if (lk == 0) {
            float4 yC = make_float4(fmaxf(fmaf(accC.x, i2, sb[32]), 0.f),
                                    fmaxf(fmaf(accC.y, i2, sb[33]), 0.f),
                                    fmaxf(fmaf(accC.z, i2, sb[34]), 0.f),
                                    fmaxf(fmaf(accC.w, i2, sb[35]), 0.f));
            *(float4*)&yrow[32] = yC;
        }
    }
    __syncwarp();

    float yv[36];
    #pragma unroll
    for (int q = 0; q < 9; q++) {
        float4 v = *(const float4*)&yrow[4 * q];
        yv[4 * q] = v.x; yv[4 * q + 1] = v.y; yv[4 * q + 2] = v.z; yv[4 * q + 3] = v.w;
    }

    // next-layer transform: lane computes quads {lk, lk+4}, lane0 also quad 8
    float pls0 = 0, pls1 = 0, pls2 = 0, pld0 = 0, pld1 = 0, pld2 = 0;
    float4* rowv = (float4*)(hout + n * ROWF);
    {
        float4 hA, hB, hC;
        #pragma unroll
        for (int k = 0; k < 4; k++) {
            int o = 4 * lk + k;
            float a = 0;
            #pragma unroll
            for (int i = 0; i < FDIM; i++) a = fmaf(yv[i], sW[o * FDIM + i], a);
            ((float*)&hA)[k] = a;
            float as = a * sas[o], av = a * sad[o];
            pls0 += as; pld0 += av;    // quad lk: head0 for lk<3, head1 for lk==3 (moved below)
        }
        if (lk == 3) { pls1 = pls0; pld1 = pld0; pls0 = 0; pld0 = 0; }
        float qls = 0, qld = 0;
        #pragma unroll
        for (int k = 0; k < 4; k++) {
            int o = 16 + 4 * lk + k;
            float a = 0;
            #pragma unroll
            for (int i = 0; i < FDIM; i++) a = fmaf(yv[i], sW[o * FDIM + i], a);
            ((float*)&hB)[k] = a;
            qls += a * sas[o]; qld += a * sad[o];
        }
        if (lk < 2) { pls1 += qls; pld1 += qld; } else { pls2 += qls; pld2 += qld; }
        rowv[lk] = hA;
        rowv[lk + 4] = hB;
        if (lk == 0) {
            #pragma unroll
            for (int k = 0; k < 4; k++) {
                int o = 32 + k;
                float a = 0;
                #pragma unroll
                for (int i = 0; i < FDIM; i++) a = fmaf(yv[i], sW[o * FDIM + i], a);
                ((float*)&hC)[k] = a;
                pls2 += a * sas[o]; pld2 += a * sad[o];
            }
            rowv[8] = hC;
        }
    }
    #pragma unroll
    for (int off = 1; off < 4; off <<= 1) {
        pls0 += __shfl_xor_sync(0xffffffffu, pls0, off);
        pls1 += __shfl_xor_sync(0xffffffffu, pls1, off);
        pls2 += __shfl_xor_sync(0xffffffffu, pls2, off);
        pld0 += __shfl_xor_sync(0xffffffffu, pld0, off);
        pld1 += __shfl_xor_sync(0xffffffffu, pld1, off);
        pld2 += __shfl_xor_sync(0xffffffffu, pld2, off);
    }
    if (lk == 1) *(float4*)&g_als[n * 4] = make_float4(pls0, pls1, pls2, 0.f);
    if (lk == 2) *(float4*)&g_ald[n * 4] = make_float4(pld0, pld1, pld2, 0.f);
}

// layer 3: aggregate + head-mean + bias + lin1 + lin2 -> out
__global__ void __launch_bounds__(256)
gather_last_kernel(const float* __restrict__ hin,
                   const float* __restrict__ b3,
                   const float* __restrict__ lin1_w,
                   const float* __restrict__ lin1_b,
                   const float* __restrict__ lin2_w,
                   const float* __restrict__ lin2_b,
                   float* __restrict__ out) {
    __shared__ __align__(16) float sy[64 * SY_STRIDE];
    __shared__ float sb[12], s1w[144], s1b[12], s2w[72], s2b[6];
    int tid = threadIdx.x;
    if (tid < 12) { sb[tid] = b3[tid]; s1b[tid] = lin1_b[tid]; }
    if (tid < 6) s2b[tid] = lin2_b[tid];
    for (int i = tid; i < 144; i += blockDim.x) s1w[i] = lin1_w[i];
    for (int i = tid; i < 72; i += blockDim.x) s2w[i] = lin2_w[i];
    __syncthreads();

    int t = blockIdx.x * blockDim.x + tid;
    int n = t >> 2;
    int lk = t & 3;
    if (n >= NNODES) return;
    float* yrow = &sy[(tid >> 2) * SY_STRIDE];

    float4 accA, accB, accC;
    float s0, s1, s2;
    aggregate4(n, lk, hin, accA, accB, accC, s0, s1, s2);

    float i0 = 1.f / (s0 + 1e-16f);
    float i1 = 1.f / (s1 + 1e-16f);
    float i2 = 1.f / (s2 + 1e-16f);
    float invA = (lk < 3) ? i0 : i1;
    float invB = (lk < 2) ? i1 : i2;

    *(float4*)&yrow[4 * lk] = make_float4(accA.x * invA, accA.y * invA, accA.z * invA, accA.w * invA);
    *(float4*)&yrow[16 + 4 * lk] = make_float4(accB.x * invB, accB.y * invB, accB.z * invB, accB.w * invB);
    if (lk == 0)
        *(float4*)&yrow[32] = make_float4(accC.x * i2, accC.y * i2, accC.z * i2, accC.w * i2);
    __syncwarp();

    if (lk == 0) {
        float o12[12];
        #pragma unroll
        for (int o = 0; o < 12; o++)
            o12[o] = (yrow[o] + yrow[o + 12] + yrow[o + 24]) * (1.f / 3.f) + sb[o];
        float tt[12];
        #pragma unroll
        for (int j = 0; j < 12; j++) {
            float a = s1b[j];
            #pragma unroll
            for (int k = 0; k < 12; k++) a = fmaf(o12[k], s1w[j * 12 + k], a);
            tt[j] = a;
        }
        float r[6];
        #pragma unroll
        for (int i = 0; i < 6; i++) {
            float a = s2b[i];
            #pragma unroll
            for (int j = 0; j < 12; j++) a = fmaf(tt[j], s2w[i * 12 + j], a);
            r[i] = a;
        }
        float2* ov = (float2*)(out + n * 6);
        ov[0] = make_float2(r[0], r[1]);
        ov[1] = make_float2(r[2], r[3]);
        ov[2] = make_float2(r[4], r[5]);
    }
}

// ---------------- launch ----------------
extern "C" void kernel_launch(void* const* d_in, const int* in_sizes, int n_in,
                              void* d_out, int out_size) {
    const float* x = (const float*)d_in[0];
    const int* ei = (const int*)d_in[1];
    int E = in_sizes[1] / 2;
    const int* src = ei;
    const int* dst = ei + E;

    const float* W[4]   = {(const float*)d_in[2],  (const float*)d_in[6],
                           (const float*)d_in[10], (const float*)d_in[14]};
    const float* asr[4] = {(const float*)d_in[3],  (const float*)d_in[7],
                           (const float*)d_in[11], (const float*)d_in[15]};
    const float* adt[4] = {(const float*)d_in[4],  (const float*)d_in[8],
                           (const float*)d_in[12], (const float*)d_in[16]};
    const float* b[4]   = {(const float*)d_in[5],  (const float*)d_in[9],
                           (const float*)d_in[13], (const float*)d_in[17]};
    const float* lin1_w = (const float*)d_in[18];
    const float* lin1_b = (const float*)d_in[19];
    const float* lin2_w = (const float*)d_in[20];
    const float* lin2_b = (const float*)d_in[21];
    float* out = (float*)d_out;

    float* hA; cudaGetSymbolAddress((void**)&hA, g_hpA);
    float* hB; cudaGetSymbolAddress((void**)&hB, g_hpB);

    int nb = (NNODES + 255) / 256;
    int eb = (E + 255) / 256;
    zero_kernel<<<nb, 256>>>();
    count_kernel<<<eb, 256>>>(dst, E);
    assign_kernel<<<nb, 256>>>();
    scatter_kernel<<<eb, 256>>>(src, dst, E);

    transform0_kernel<<<nb, 256>>>(x, W[0], asr[0], adt[0], hA);

    int gb = (NNODES * 4 + 255) / 256;
    edgew_kernel<<<eb, 256>>>(E);
    gather_fused_kernel<<<gb, 256>>>(hA, hB, b[0], W[1], asr[1], adt[1]);
    edgew_kernel<<<eb, 256>>>(E);
    gather_fused_kernel<<<gb, 256>>>(hB, hA, b[1], W[2], asr[2], adt[2]);
    edgew_kernel<<<eb, 256>>>(E);
    gather_fused_kernel<<<gb, 256>>>(hA, hB, b[2], W[3], asr[3], adt[3]);
    edgew_kernel<<<eb, 256>>>(E);
    gather_last_kernel<<<gb, 256>>>(hB, b[3], lin1_w, lin1_b, lin2_w, lin2_b, out);
}

// round 7
// speedup vs baseline: 1.3927x; 1.2618x over previous
#include <cuda_runtime.h>

#define NNODES 50000
#define FDIM 36
#define ROWF 40                 // 36 h + 3 als + pad = 160B row (5 sectors exactly)
#define EMAX 800000

// ---------------- persistent device scratch ----------------
__device__ __align__(16) float g_hpA[NNODES * ROWF];
__device__ __align__(16) float g_hpB[NNODES * ROWF];
__device__ __align__(16) float g_y[NNODES * FDIM];
__device__ __align__(16) float g_ald[NNODES * 4];
__device__ int g_deg[NNODES];
__device__ int g_rowstart[NNODES];
__device__ int g_rank[EMAX];
__device__ int g_col[EMAX];
__device__ int g_total;

__device__ __forceinline__ float lrelu(float x) { return fmaxf(x, 0.2f * x); }

// ---------------- CSR build ----------------
__global__ void zero_kernel() {
    int i = blockIdx.x * blockDim.x + threadIdx.x;
    if (i < NNODES) g_deg[i] = 0;
    if (i == 0) g_total = 0;
}

__global__ void count_kernel(const int* __restrict__ dst, int E) {
    int i = blockIdx.x * blockDim.x + threadIdx.x;
    if (i < E) g_rank[i] = atomicAdd(&g_deg[dst[i]], 1);
}

__global__ void assign_kernel() {
    int i = blockIdx.x * blockDim.x + threadIdx.x;
    int lane = threadIdx.x & 31;
    int v = (i < NNODES) ? g_deg[i] : 0;
    int x = v;
    #pragma unroll
    for (int off = 1; off < 32; off <<= 1) {
        int t = __shfl_up_sync(0xffffffffu, x, off);
        if (lane >= off) x += t;
    }
    int wsum = __shfl_sync(0xffffffffu, x, 31);
    int base = 0;
    if (lane == 31) base = atomicAdd(&g_total, wsum);
    base = __shfl_sync(0xffffffffu, base, 31);
    if (i < NNODES) g_rowstart[i] = base + x - v;
}

__global__ void scatter_kernel(const int* __restrict__ src, const int* __restrict__ dst, int E) {
    int i = blockIdx.x * blockDim.x + threadIdx.x;
    if (i < E) {
        int d = dst[i];
        g_col[g_rowstart[d] + g_rank[i]] = src[i];
    }
}

// ---------------- layer-0 transform: h = x @ W0^T (in=24) ----------------
__global__ void transform0_kernel(const float* __restrict__ xin,
                                  const float* __restrict__ W,
                                  const float* __restrict__ a_src,
                                  const float* __restrict__ a_dst,
                                  float* __restrict__ hout) {
    __shared__ float sW[FDIM * 24];
    __shared__ float sas[FDIM], sad[FDIM];
    int tid = threadIdx.x;
    for (int i = tid; i < FDIM * 24; i += blockDim.x) sW[i] = W[i];
    if (tid < FDIM) { sas[tid] = a_src[tid]; sad[tid] = a_dst[tid]; }
    __syncthreads();
    int n = blockIdx.x * blockDim.x + tid;
    if (n >= NNODES) return;

    float yr[24];
    const float4* xv = (const float4*)(xin + n * 24);
    #pragma unroll
    for (int q = 0; q < 6; q++) {
        float4 v = xv[q];
        yr[4 * q] = v.x; yr[4 * q + 1] = v.y; yr[4 * q + 2] = v.z; yr[4 * q + 3] = v.w;
    }

    float als0 = 0, als1 = 0, als2 = 0, ald0 = 0, ald1 = 0, ald2 = 0;
    float4* rowv = (float4*)(hout + n * ROWF);
    #pragma unroll
    for (int q = 0; q < 9; q++) {
        float4 hv;
        #pragma unroll
        for (int k = 0; k < 4; k++) {
            int o = q * 4 + k;
            float a = 0;
            #pragma unroll
            for (int i = 0; i < 24; i++) a = fmaf(yr[i], sW[o * 24 + i], a);
            ((float*)&hv)[k] = a;
            float as = a * sas[o], av = a * sad[o];
            if (q < 3)      { als0 += as; ald0 += av; }
            else if (q < 6) { als1 += as; ald1 += av; }
            else            { als2 += as; ald2 += av; }
        }
        rowv[q] = hv;
    }
    rowv[9] = make_float4(als0, als1, als2, 0.f);
    *(float4*)&g_ald[n * 4] = make_float4(ald0, ald1, ald2, 0.f);
}

// ---------------- mid transform: h = y @ W^T (36 -> 36) ----------------
__global__ void transform_mid_kernel(const float* __restrict__ W,
                                     const float* __restrict__ a_src,
                                     const float* __restrict__ a_dst,
                                     float* __restrict__ hout) {
    __shared__ float sW[FDIM * FDIM];
    __shared__ float sas[FDIM], sad[FDIM];
    int tid = threadIdx.x;
    for (int i = tid; i < FDIM * FDIM; i += blockDim.x) sW[i] = W[i];
    if (tid < FDIM) { sas[tid] = a_src[tid]; sad[tid] = a_dst[tid]; }
    __syncthreads();
    int n = blockIdx.x * blockDim.x + tid;
    if (n >= NNODES) return;

    float yr[FDIM];
    const float4* yv = (const float4*)(g_y + n * FDIM);
    #pragma unroll
    for (int q = 0; q < 9; q++) {
        float4 v = yv[q];
        yr[4 * q] = v.x; yr[4 * q + 1] = v.y; yr[4 * q + 2] = v.z; yr[4 * q + 3] = v.w;
    }

    float als0 = 0, als1 = 0, als2 = 0, ald0 = 0, ald1 = 0, ald2 = 0;
    float4* rowv = (float4*)(hout + n * ROWF);
    #pragma unroll
    for (int q = 0; q < 9; q++) {
        float4 hv;
        #pragma unroll
        for (int k = 0; k < 4; k++) {
            int o = q * 4 + k;
            float a = 0;
            #pragma unroll
            for (int i = 0; i < FDIM; i++) a = fmaf(yr[i], sW[o * FDIM + i], a);
            ((float*)&hv)[k] = a;
            float as = a * sas[o], av = a * sad[o];
            if (q < 3)      { als0 += as; ald0 += av; }
            else if (q < 6) { als1 += as; ald1 += av; }
            else            { als2 += as; ald2 += av; }
        }
        rowv[q] = hv;
    }
    rowv[9] = make_float4(als0, als1, als2, 0.f);
    *(float4*)&g_ald[n * 4] = make_float4(ald0, ald1, ald2, 0.f);
}

// ---------------- head-per-lane gather: 3 lanes per node ----------------
// lane h of node n accumulates its head's 12 features; writes normalized y.
template <bool RELU>
__global__ void __launch_bounds__(192)
gather_head_kernel(const float* __restrict__ hin,
                   const float* __restrict__ bias) {
    __shared__ float sb[FDIM];
    int tid = threadIdx.x;
    if (RELU) {
        if (tid < FDIM) sb[tid] = bias[tid];
        __syncthreads();
    }

    int t = blockIdx.x * blockDim.x + tid;
    int n = t / 3;
    int h = t - 3 * n;
    if (n >= NNODES) return;

    int beg = g_rowstart[n];
    int end = beg + g_deg[n];
    float aldh = g_ald[n * 4 + h];
    int fo = 12 * h;               // feature offset of this head

    // self loop
    const float* self = hin + n * ROWF;
    float wself = __expf(lrelu(self[36 + h] + aldh));
    float s = wself;
    float4 a0, a1, a2;
    {
        float4 v0 = *(const float4*)(self + fo);
        float4 v1 = *(const float4*)(self + fo + 4);
        float4 v2 = *(const float4*)(self + fo + 8);
        a0 = make_float4(wself * v0.x, wself * v0.y, wself * v0.z, wself * v0.w);
        a1 = make_float4(wself * v1.x, wself * v1.y, wself * v1.z, wself * v1.w);
        a2 = make_float4(wself * v2.x, wself * v2.y, wself * v2.z, wself * v2.w);
    }

    #pragma unroll 2
    for (int j = beg; j < end; j++) {
        int sn = g_col[j];
        const float* r = hin + sn * ROWF;
        float a = r[36 + h];
        float4 v0 = *(const float4*)(r + fo);
        float4 v1 = *(const float4*)(r + fo + 4);
        float4 v2 = *(const float4*)(r + fo + 8);
        float w = __expf(lrelu(a + aldh));
        s += w;
        a0.x = fmaf(w, v0.x, a0.x); a0.y = fmaf(w, v0.y, a0.y);
        a0.z = fmaf(w, v0.z, a0.z); a0.w = fmaf(w, v0.w, a0.w);
        a1.x = fmaf(w, v1.x, a1.x); a1.y = fmaf(w, v1.y, a1.y);
        a1.z = fmaf(w, v1.z, a1.z); a1.w = fmaf(w, v1.w, a1.w);
        a2.x = fmaf(w, v2.x, a2.x); a2.y = fmaf(w, v2.y, a2.y);
        a2.z = fmaf(w, v2.z, a2.z); a2.w = fmaf(w, v2.w, a2.w);
    }

    float inv = 1.f / (s + 1e-16f);
    float* yr = g_y + n * FDIM + fo;
    if (RELU) {
        const float* b = sb + fo;
        *(float4*)yr = make_float4(fmaxf(fmaf(a0.x, inv, b[0]), 0.f),
                                   fmaxf(fmaf(a0.y, inv, b[1]), 0.f),
                                   fmaxf(fmaf(a0.z, inv, b[2]), 0.f),
                                   fmaxf(fmaf(a0.w, inv, b[3]), 0.f));
        *(float4*)(yr + 4) = make_float4(fmaxf(fmaf(a1.x, inv, b[4]), 0.f),
                                         fmaxf(fmaf(a1.y, inv, b[5]), 0.f),
                                         fmaxf(fmaf(a1.z, inv, b[6]), 0.f),
                                         fmaxf(fmaf(a1.w, inv, b[7]), 0.f));
        *(float4*)(yr + 8) = make_float4(fmaxf(fmaf(a2.x, inv, b[8]), 0.f),
                                         fmaxf(fmaf(a2.y, inv, b[9]), 0.f),
                                         fmaxf(fmaf(a2.z, inv, b[10]), 0.f),
                                         fmaxf(fmaf(a2.w, inv, b[11]), 0.f));
    } else {
        *(float4*)yr       = make_float4(a0.x * inv, a0.y * inv, a0.z * inv, a0.w * inv);
        *(float4*)(yr + 4) = make_float4(a1.x * inv, a1.y * inv, a1.z * inv, a1.w * inv);
        *(float4*)(yr + 8) = make_float4(a2.x * inv, a2.y * inv, a2.z * inv, a2.w * inv);
    }
}

// ---------------- final: head-mean + b3 + lin1 + lin2 ----------------
__global__ void final_kernel(const float* __restrict__ b3,
                             const float* __restrict__ lin1_w,
                             const float* __restrict__ lin1_b,
                             const float* __restrict__ lin2_w,
                             const float* __restrict__ lin2_b,
                             float* __restrict__ out) {
    __shared__ float sb[12], s1w[144], s1b[12], s2w[72], s2b[6];
    int tid = threadIdx.x;
    if (tid < 12) { sb[tid] = b3[tid]; s1b[tid] = lin1_b[tid]; }
    if (tid < 6) s2b[tid] = lin2_b[tid];
    for (int i = tid; i < 144; i += blockDim.x) s1w[i] = lin1_w[i];
    for (int i = tid; i < 72; i += blockDim.x) s2w[i] = lin2_w[i];
    __syncthreads();
    int n = blockIdx.x * blockDim.x + tid;
    if (n >= NNODES) return;

    float yv[FDIM];
    const float4* yp = (const float4*)(g_y + n * FDIM);
    #pragma unroll
    for (int q = 0; q < 9; q++) {
        float4 v = yp[q];
        yv[4 * q] = v.x; yv[4 * q + 1] = v.y; yv[4 * q + 2] = v.z; yv[4 * q + 3] = v.w;
    }

    float o12[12];
    #pragma unroll
    for (int o = 0; o < 12; o++)
        o12[o] = (yv[o] + yv[o + 12] + yv[o + 24]) * (1.f / 3.f) + sb[o];

    float tt[12];
    #pragma unroll
    for (int j = 0; j < 12; j++) {
        float a = s1b[j];
        #pragma unroll
        for (int k = 0; k < 12; k++) a = fmaf(o12[k], s1w[j * 12 + k], a);
        tt[j] = a;
    }
    float r[6];
    #pragma unroll
    for (int i = 0; i < 6; i++) {
        float a = s2b[i];
        #pragma unroll
        for (int j = 0; j < 12; j++) a = fmaf(tt[j], s2w[i * 12 + j], a);
        r[i] = a;
    }
    float2* ov = (float2*)(out + n * 6);
    ov[0] = make_float2(r[0], r[1]);
    ov[1] = make_float2(r[2], r[3]);
    ov[2] = make_float2(r[4], r[5]);
}

// ---------------- launch ----------------
extern "C" void kernel_launch(void* const* d_in, const int* in_sizes, int n_in,
                              void* d_out, int out_size) {
    const float* x = (const float*)d_in[0];
    const int* ei = (const int*)d_in[1];
    int E = in_sizes[1] / 2;
    const int* src = ei;
    const int* dst = ei + E;

    const float* W[4]   = {(const float*)d_in[2],  (const float*)d_in[6],
                           (const float*)d_in[10], (const float*)d_in[14]};
    const float* asr[4] = {(const float*)d_in[3],  (const float*)d_in[7],
                           (const float*)d_in[11], (const float*)d_in[15]};
    const float* adt[4] = {(const float*)d_in[4],  (const float*)d_in[8],
                           (const float*)d_in[12], (const float*)d_in[16]};
    const float* b[4]   = {(const float*)d_in[5],  (const float*)d_in[9],
                           (const float*)d_in[13], (const float*)d_in[17]};
    const float* lin1_w = (const float*)d_in[18];
    const float* lin1_b = (const float*)d_in[19];
    const float* lin2_w = (const float*)d_in[20];
    const float* lin2_b = (const float*)d_in[21];
    float* out = (float*)d_out;

    float* hA; cudaGetSymbolAddress((void**)&hA, g_hpA);
    float* hB; cudaGetSymbolAddress((void**)&hB, g_hpB);

    int nb = (NNODES + 255) / 256;
    int eb = (E + 255) / 256;
    zero_kernel<<<nb, 256>>>();
    count_kernel<<<eb, 256>>>(dst, E);
    assign_kernel<<<nb, 256>>>();
    scatter_kernel<<<eb, 256>>>(src, dst, E);

    transform0_kernel<<<nb, 256>>>(x, W[0], asr[0], adt[0], hA);

    int gb = (NNODES * 3 + 191) / 192;
    gather_head_kernel<true><<<gb, 192>>>(hA, b[0]);
    transform_mid_kernel<<<nb, 256>>>(W[1], asr[1], adt[1], hB);
    gather_head_kernel<true><<<gb, 192>>>(hB, b[1]);
    transform_mid_kernel<<<nb, 256>>>(W[2], asr[2], adt[2], hA);
    gather_head_kernel<true><<<gb, 192>>>(hA, b[2]);
    transform_mid_kernel<<<nb, 256>>>(W[3], asr[3], adt[3], hB);
    gather_head_kernel<false><<<gb, 192>>>(hB, nullptr);
    final_kernel<<<nb, 256>>>(b[3], lin1_w, lin1_b, lin2_w, lin2_b, out);
}